// round 10
// baseline (speedup 1.0000x reference)
#include <cuda_runtime.h>
#include <cuda_bf16.h>
#include <mma.h>

using namespace nvcuda;

#define TB 16      // batch
#define TT 128     // time steps
#define TE 1024    // embed dim
#define TH 1024    // hidden dim
#define TV 32000   // vocab
#define BH (TB*TH)

// ---------------- scratch state (device globals: allocation-free) ----------
__device__ float g_x[(size_t)TT * TB * TE];       // [T][B][E] gathered embeddings
__device__ float g_h0[2][BH];
__device__ float g_c0[2][BH];
__device__ float g_h1[2][BH];
__device__ float g_c1[2][BH];
__device__ float g_feats[(size_t)TB * TT * TH];   // [B][T][H]
__device__ float g_zero[BH];                      // never written -> stays 0

// ---------------- embedding gather ----------------------------------------
__global__ void embed_gather_kernel(const int* __restrict__ ids,
                                    const float* __restrict__ embed) {
    int tb = blockIdx.x;            // t*TB + b
    int t  = tb >> 4;
    int b  = tb & 15;
    int id = ids[b * TT + t];
    const float4* src = (const float4*)(embed + (size_t)id * TE);
    float4*       dst = (float4*)(g_x + (size_t)tb * TE);
    dst[threadIdx.x] = src[threadIdx.x];   // 256 threads x float4 = 1024
}

// ---------------- state init ----------------------------------------------
__global__ void init_states_kernel(const float* __restrict__ eh,
                                   const float* __restrict__ ec) {
    int i = blockIdx.x * blockDim.x + threadIdx.x;   // BH total
    g_h0[0][i] = eh[i];
    g_h1[0][i] = eh[BH + i];
    g_c0[0][i] = ec[i];
    g_c1[0][i] = ec[BH + i];
}

// ---------------- LSTM step core ------------------------------------------
__device__ __forceinline__ float sigmoidf_(float x) {
    return 1.0f / (1.0f + __expf(-x));
}

// One source phase of K=1024: accumulate all 4 gates x 16 batches for unit j.
// src: [16][1024] activations; wmat row-major with row stride wstride; column
// offset coff selects which 1024-column slab of the weight matrix to use.
__device__ __forceinline__ void lstm_phase(
    const float* __restrict__ src, const float* __restrict__ wmat,
    int wstride, int coff, int j, int lane,
    float (&acc)[4][16], float (*s_in)[128])
{
    for (int c = 0; c < 8; ++c) {
        // cooperative load of 16x128 activation chunk (2048 floats / 256 thr)
        const float4* s4 = (const float4*)src;
        #pragma unroll
        for (int i = 0; i < 2; ++i) {
            int slot = threadIdx.x + (i << 8);   // 0..511 float4 slots
            int b  = slot >> 5;
            int kk = slot & 31;
            ((float4*)s_in[b])[kk] = s4[(b << 8) + (c << 5) + kk];
        }
        __syncthreads();

        int col = coff + (c << 7) + (lane << 2);
        float4 wv0 = *(const float4*)&wmat[(size_t)(0 * TH + j) * wstride + col];
        float4 wv1 = *(const float4*)&wmat[(size_t)(1 * TH + j) * wstride + col];
        float4 wv2 = *(const float4*)&wmat[(size_t)(2 * TH + j) * wstride + col];
        float4 wv3 = *(const float4*)&wmat[(size_t)(3 * TH + j) * wstride + col];

        #pragma unroll
        for (int b = 0; b < 16; ++b) {
            float4 xv = *(const float4*)&s_in[b][lane << 2];
            acc[0][b] += wv0.x * xv.x + wv0.y * xv.y + wv0.z * xv.z + wv0.w * xv.w;
            acc[1][b] += wv1.x * xv.x + wv1.y * xv.y + wv1.z * xv.z + wv1.w * xv.w;
            acc[2][b] += wv2.x * xv.x + wv2.y * xv.y + wv2.z * xv.z + wv2.w * xv.w;
            acc[3][b] += wv3.x * xv.x + wv3.y * xv.y + wv3.z * xv.z + wv3.w * xv.w;
        }
        __syncthreads();
    }
}

__device__ __forceinline__ void lstm_finish(
    float (&acc)[4][16], float (*s_red)[64], int warp, int lane, int j,
    const float* __restrict__ cprev,
    const float* __restrict__ bih, const float* __restrict__ bhh,
    float* __restrict__ hout, float* __restrict__ cout,
    float* __restrict__ feats, int t)
{
    // warp butterfly reduce each of the 64 partial sums
    #pragma unroll
    for (int g = 0; g < 4; ++g)
        #pragma unroll
        for (int b = 0; b < 16; ++b)
            #pragma unroll
            for (int off = 16; off; off >>= 1)
                acc[g][b] += __shfl_xor_sync(0xffffffffu, acc[g][b], off);

    if (lane == 0) {
        #pragma unroll
        for (int g = 0; g < 4; ++g)
            #pragma unroll
            for (int b = 0; b < 16; ++b)
                s_red[warp][g * 16 + b] = acc[g][b];
    }
    __syncwarp();

    if (lane < 16) {
        int b = lane;
        float gi = s_red[warp][0 * 16 + b] + bih[j]           + bhh[j];
        float gf = s_red[warp][1 * 16 + b] + bih[TH + j]      + bhh[TH + j];
        float gg = s_red[warp][2 * 16 + b] + bih[2 * TH + j]  + bhh[2 * TH + j];
        float go = s_red[warp][3 * 16 + b] + bih[3 * TH + j]  + bhh[3 * TH + j];
        float cold = cprev[b * TH + j];
        float cn = sigmoidf_(gf) * cold + sigmoidf_(gi) * tanhf(gg);
        float hn = sigmoidf_(go) * tanhf(cn);
        cout[b * TH + j] = cn;
        hout[b * TH + j] = hn;
        if (feats) feats[((size_t)b * TT + t) * TH + j] = hn;
    }
}

__global__ __launch_bounds__(256) void lstm_layer0_kernel(
    const float* __restrict__ Wih, const float* __restrict__ Whh,
    const float* __restrict__ bih, const float* __restrict__ bhh, int t)
{
    __shared__ float s_in[16][128];
    __shared__ float s_red[8][64];
    int warp = threadIdx.x >> 5, lane = threadIdx.x & 31;
    int j = (blockIdx.x << 3) + warp;

    float acc[4][16];
    #pragma unroll
    for (int g = 0; g < 4; ++g)
        #pragma unroll
        for (int b = 0; b < 16; ++b) acc[g][b] = 0.f;

    int r = t & 1, w = 1 - r;
    const float* xsrc = g_x + (size_t)t * TB * TE;
    const float* feed = (t == 0) ? g_zero : g_h1[r];

    lstm_phase(xsrc,    Wih, 2048, 0,    j, lane, acc, s_in);
    lstm_phase(feed,    Wih, 2048, 1024, j, lane, acc, s_in);
    lstm_phase(g_h0[r], Whh, 1024, 0,    j, lane, acc, s_in);

    lstm_finish(acc, s_red, warp, lane, j, g_c0[r], bih, bhh,
                g_h0[w], g_c0[w], nullptr, t);
}

__global__ __launch_bounds__(256) void lstm_layer1_kernel(
    const float* __restrict__ Wih, const float* __restrict__ Whh,
    const float* __restrict__ bih, const float* __restrict__ bhh, int t)
{
    __shared__ float s_in[16][128];
    __shared__ float s_red[8][64];
    int warp = threadIdx.x >> 5, lane = threadIdx.x & 31;
    int j = (blockIdx.x << 3) + warp;

    float acc[4][16];
    #pragma unroll
    for (int g = 0; g < 4; ++g)
        #pragma unroll
        for (int b = 0; b < 16; ++b) acc[g][b] = 0.f;

    int r = t & 1, w = 1 - r;

    lstm_phase(g_h0[w], Wih, 1024, 0, j, lane, acc, s_in);  // new h0 (this step)
    lstm_phase(g_h1[r], Whh, 1024, 0, j, lane, acc, s_in);

    lstm_finish(acc, s_red, warp, lane, j, g_c1[r], bih, bhh,
                g_h1[w], g_c1[w], g_feats, t);
}

// ---------------- output projection: tf32 WMMA GEMM ------------------------
// logits[m, n] = sum_k feats[m, k] * Wout[n, k] + bout[n]
// CTA tile 64x64, 4 warps (2x2), warp tile 32x32 via 2x2 m16n16k8 fragments.
__global__ __launch_bounds__(128) void proj_kernel(
    const float* __restrict__ Wout, const float* __restrict__ bout,
    float* __restrict__ out)
{
    __shared__ float smem[2 * 64 * 40];
    float (*sA)[40] = (float(*)[40])smem;
    float (*sB)[40] = (float(*)[40])(smem + 64 * 40);

    int mblk = blockIdx.x << 6;
    int nblk = blockIdx.y << 6;
    int warp = threadIdx.x >> 5;
    int wm = (warp >> 1) * 32;
    int wn = (warp & 1) * 32;

    wmma::fragment<wmma::accumulator, 16, 16, 8, float> cf[2][2];
    #pragma unroll
    for (int mi = 0; mi < 2; ++mi)
        #pragma unroll
        for (int ni = 0; ni < 2; ++ni)
            wmma::fill_fragment(cf[mi][ni], 0.0f);

    const float* A = g_feats;
    for (int k0 = 0; k0 < 1024; k0 += 32) {
        #pragma unroll
        for (int i = 0; i < 4; ++i) {
            int slot = threadIdx.x + (i << 7);  // 0..511 float4 slots
            int row  = slot >> 3;
            int c4   = (slot & 7) << 2;
            *(float4*)&sA[row][c4] =
                *(const float4*)&A[(size_t)(mblk + row) * 1024 + k0 + c4];
            *(float4*)&sB[row][c4] =
                *(const float4*)&Wout[(size_t)(nblk + row) * 1024 + k0 + c4];
        }
        __syncthreads();

        #pragma unroll
        for (int kk = 0; kk < 32; kk += 8) {
            wmma::fragment<wmma::matrix_a, 16, 16, 8,
                           wmma::precision::tf32, wmma::row_major> af[2];
            wmma::fragment<wmma::matrix_b, 16, 16, 8,
                           wmma::precision::tf32, wmma::col_major> bf[2];
            #pragma unroll
            for (int i = 0; i < 2; ++i) {
                wmma::load_matrix_sync(af[i], &sA[wm + i * 16][kk], 40);
                #pragma unroll
                for (int e = 0; e < af[i].num_elements; ++e)
                    af[i].x[e] = wmma::__float_to_tf32(af[i].x[e]);
                wmma::load_matrix_sync(bf[i], &sB[wn + i * 16][kk], 40);
                #pragma unroll
                for (int e = 0; e < bf[i].num_elements; ++e)
                    bf[i].x[e] = wmma::__float_to_tf32(bf[i].x[e]);
            }
            #pragma unroll
            for (int mi = 0; mi < 2; ++mi)
                #pragma unroll
                for (int ni = 0; ni < 2; ++ni)
                    wmma::mma_sync(cf[mi][ni], af[mi], bf[ni], cf[mi][ni]);
        }
        __syncthreads();
    }

    // epilogue: stage C in smem, add bias, vectorized store
    float (*sC)[68] = (float(*)[68])smem;   // 64*68 = 4352 floats <= 5120
    #pragma unroll
    for (int mi = 0; mi < 2; ++mi)
        #pragma unroll
        for (int ni = 0; ni < 2; ++ni)
            wmma::store_matrix_sync(&sC[wm + mi * 16][wn + ni * 16],
                                    cf[mi][ni], 68, wmma::mem_row_major);
    __syncthreads();

    #pragma unroll
    for (int i = 0; i < 8; ++i) {
        int slot = threadIdx.x + (i << 7);  // 0..1023 float4 slots
        int row  = slot >> 4;
        int c4   = (slot & 15) << 2;
        float4 v  = *(float4*)&sC[row][c4];
        float4 bv = *(const float4*)&bout[nblk + c4];
        v.x += bv.x; v.y += bv.y; v.z += bv.z; v.w += bv.w;
        *(float4*)&out[(size_t)(mblk + row) * TV + nblk + c4] = v;
    }
}

// ---------------- launch ----------------------------------------------------
extern "C" void kernel_launch(void* const* d_in, const int* in_sizes, int n_in,
                              void* d_out, int out_size) {
    const int*   ids  = (const int*)d_in[0];
    const float* ench = (const float*)d_in[1];
    const float* encc = (const float*)d_in[2];
    const float* emb  = (const float*)d_in[3];
    const float* Wih0 = (const float*)d_in[4];
    const float* Whh0 = (const float*)d_in[5];
    const float* bih0 = (const float*)d_in[6];
    const float* bhh0 = (const float*)d_in[7];
    const float* Wih1 = (const float*)d_in[8];
    const float* Whh1 = (const float*)d_in[9];
    const float* bih1 = (const float*)d_in[10];
    const float* bhh1 = (const float*)d_in[11];
    const float* Wout = (const float*)d_in[12];
    const float* bout = (const float*)d_in[13];
    float* out = (float*)d_out;

    embed_gather_kernel<<<TT * TB, 256>>>(ids, emb);
    init_states_kernel<<<64, 256>>>(ench, encc);

    for (int t = 0; t < TT; ++t) {
        lstm_layer0_kernel<<<128, 256>>>(Wih0, Whh0, bih0, bhh0, t);
        lstm_layer1_kernel<<<128, 256>>>(Wih1, Whh1, bih1, bhh1, t);
    }

    proj_kernel<<<dim3(32, 500), 128>>>(Wout, bout, out);
}

// round 12
// speedup vs baseline: 1.0307x; 1.0307x over previous
#include <cuda_runtime.h>
#include <cuda_bf16.h>
#include <mma.h>

using namespace nvcuda;

#define TB 16      // batch
#define TT 128     // time steps
#define TE 1024    // embed dim
#define TH 1024    // hidden dim
#define TV 32000   // vocab
#define BH (TB*TH)

#define GRID_R 128   // persistent recurrence CTAs
#define KC 128       // k-chunk size

// ---------------- scratch state (device globals: allocation-free) ----------
__device__ float g_x[(size_t)TT * TB * TE];        // [T][B][E] embeddings
__device__ float g_g0x[(size_t)TT * TB * 4 * TH];  // [T*B][4H] x-gates (+b0)
__device__ float g_h0[2][BH];
__device__ float g_h1[2][BH];
__device__ float g_feats[(size_t)TB * TT * TH];    // [B][T][H]
__device__ unsigned g_barctr;

// ---------------- embedding gather ----------------------------------------
__global__ void embed_gather_kernel(const int* __restrict__ ids,
                                    const float* __restrict__ embed) {
    int tb = blockIdx.x;            // t*TB + b
    int t  = tb >> 4;
    int b  = tb & 15;
    int id = ids[b * TT + t];
    const float4* src = (const float4*)(embed + (size_t)id * TE);
    float4*       dst = (float4*)(g_x + (size_t)tb * TE);
    dst[threadIdx.x] = src[threadIdx.x];   // 256 threads x float4 = 1024
}

__global__ void reset_kernel() { g_barctr = 0u; }

// ---------------- helpers ---------------------------------------------------
__device__ __forceinline__ unsigned ld_acq(const unsigned* p) {
    unsigned v;
    asm volatile("ld.acquire.gpu.u32 %0, [%1];" : "=r"(v) : "l"(p) : "memory");
    return v;
}
__device__ __forceinline__ void grid_barrier(unsigned tgt) {
    __syncthreads();
    if (threadIdx.x == 0) {
        __threadfence();
        atomicAdd(&g_barctr, 1u);
        while (ld_acq(&g_barctr) < tgt) {}
    }
    __syncthreads();
}
__device__ __forceinline__ void cp16(void* dst, const void* src) {
    unsigned d = (unsigned)__cvta_generic_to_shared(dst);
    asm volatile("cp.async.cg.shared.global [%0], [%1], 16;" :: "r"(d), "l"(src));
}
__device__ __forceinline__ float sigmoidf_(float x) {
    return 1.0f / (1.0f + __expf(-x));
}

// ---------------- smem layout (floats) -------------------------------------
#define SM_SW   0                       // [2][32][132] weight chunk buffers
#define SM_SA   (2*32*132)              // [2][16][132] activation buffers
#define SM_RED  (SM_SA + 2*16*132)      // [4][16][36]  per-kq partials
#define SM_C0   (SM_RED + 4*16*36)      // [128] c-state L0
#define SM_C1   (SM_C0 + 128)           // [128] c-state L1
#define SM_B1   (SM_C1 + 128)           // [32]  fused L1 bias
#define SM_FLOATS (SM_B1 + 32)
#define SMEM_RECUR (SM_FLOATS * 4)      // 61056 B

// ---------------- fused two-phase mat-mul for one layer (3xTF32) -----------
// CTA owns 32 gate rows rr=g*8+u -> global weight row g*TH + j0 + u.
// Warp w: tw=w&1 picks 16-row half; kq=w>>1 picks 32-col quarter of each
// 128-col k-chunk. 16 chunks total = phase0 K=1024 then phase1 K=1024.
// Error-compensated: v = hi + lo (both tf32); acc += hi*hi, accc += hi*lo+lo*hi.
__device__ __forceinline__ void layer_mma(
    float* sm, int j0, int tw, int kq,
    const float* A0, const float* W0, int ld0, int co0,
    const float* A1, const float* W1, int ld1, int co1,
    int i0,
    wmma::fragment<wmma::accumulator,16,16,8,float>& acc,
    wmma::fragment<wmma::accumulator,16,16,8,float>& accc)
{
    float (*sWb)[32][132] = (float(*)[32][132])(sm + SM_SW);
    float (*sAb)[16][132] = (float(*)[16][132])(sm + SM_SA);
    int tid = threadIdx.x;

    auto stage = [&](int i, int buf) {
        int ph = i >> 3;
        int k0 = (i & 7) * KC;
        const float* Aptr = ph ? A1 : A0;
        const float* Wptr = ph ? W1 : W0;
        int ld = ph ? ld1 : ld0;
        int co = ph ? co1 : co0;
        #pragma unroll
        for (int l = 0; l < 4; ++l) {                 // W: 32x128 = 1024 float4
            int idx = tid + (l << 8);
            int rr = idx >> 5;
            int c4 = (idx & 31) << 2;
            int g = rr >> 3, u = rr & 7;
            cp16(&sWb[buf][rr][c4],
                 Wptr + (size_t)(g * TH + j0 + u) * ld + co + k0 + c4);
        }
        #pragma unroll
        for (int l = 0; l < 2; ++l) {                 // A: 16x128 = 512 float4
            int idx = tid + (l << 8);
            int b = idx >> 5;
            int c4 = (idx & 31) << 2;
            cp16(&sAb[buf][b][c4], Aptr + b * TH + k0 + c4);
        }
        asm volatile("cp.async.commit_group;" ::: "memory");
    };

    stage(i0, 0);
    for (int i = i0; i < 16; ++i) {
        int buf = (i - i0) & 1;
        if (i + 1 < 16) {
            stage(i + 1, buf ^ 1);
            asm volatile("cp.async.wait_group 1;" ::: "memory");
        } else {
            asm volatile("cp.async.wait_group 0;" ::: "memory");
        }
        __syncthreads();
        #pragma unroll
        for (int ks = 0; ks < 4; ++ks) {
            int k = (kq << 5) + (ks << 3);
            wmma::fragment<wmma::matrix_a,16,16,8,wmma::precision::tf32,wmma::row_major> af, afl;
            wmma::fragment<wmma::matrix_b,16,16,8,wmma::precision::tf32,wmma::col_major> bf, bfl;
            wmma::load_matrix_sync(af, &sAb[buf][0][k], 132);
            wmma::load_matrix_sync(bf, &sWb[buf][tw << 4][k], 132);
            #pragma unroll
            for (int e = 0; e < af.num_elements; ++e) {
                float v  = af.x[e];
                float hi = wmma::__float_to_tf32(v);
                af.x[e]  = hi;
                afl.x[e] = wmma::__float_to_tf32(v - hi);
            }
            #pragma unroll
            for (int e = 0; e < bf.num_elements; ++e) {
                float v  = bf.x[e];
                float hi = wmma::__float_to_tf32(v);
                bf.x[e]  = hi;
                bfl.x[e] = wmma::__float_to_tf32(v - hi);
            }
            wmma::mma_sync(acc,  af,  bf,  acc);
            wmma::mma_sync(accc, af,  bfl, accc);
            wmma::mma_sync(accc, afl, bf,  accc);
        }
        __syncthreads();
    }
}

// ---------------- persistent recurrence kernel ------------------------------
__global__ void __launch_bounds__(256, 1) recur_kernel(
    const float* __restrict__ eh, const float* __restrict__ ec,
    const float* __restrict__ Wih0, const float* __restrict__ Whh0,
    const float* __restrict__ Wih1, const float* __restrict__ Whh1,
    const float* __restrict__ bih1, const float* __restrict__ bhh1)
{
    extern __shared__ float sm[];
    float (*sRed)[16][36] = (float(*)[16][36])(sm + SM_RED);
    float* sC0 = sm + SM_C0;
    float* sC1 = sm + SM_C1;
    float* sB1 = sm + SM_B1;

    int cta = blockIdx.x;
    int j0  = cta << 3;               // 8 hidden units per CTA
    int tid = threadIdx.x;
    int w   = tid >> 5;
    int tw  = w & 1;
    int kq  = w >> 1;

    // init: c-state into smem (lives there all 128 steps), h into globals
    if (tid < 128) {
        int b = tid >> 3, u = tid & 7;
        sC0[tid] = ec[b * TH + j0 + u];
        sC1[tid] = ec[BH + b * TH + j0 + u];
        g_h0[0][b * TH + j0 + u] = eh[b * TH + j0 + u];
        g_h1[0][b * TH + j0 + u] = eh[BH + b * TH + j0 + u];
    } else if (tid < 160) {
        int r = tid - 128;
        int g = r >> 3, u = r & 7;
        sB1[r] = bih1[g * TH + j0 + u] + bhh1[g * TH + j0 + u];
    }
    unsigned tgt = GRID_R;
    grid_barrier(tgt);

    for (int t = 0; t < TT; ++t) {
        int p = t & 1;
        wmma::fragment<wmma::accumulator,16,16,8,float> acc, accc;

        // ------- layer 0: feed @ Wih0[:,1024:] + h0 @ Whh0 (+ g0x) -------
        wmma::fill_fragment(acc, 0.0f);
        wmma::fill_fragment(accc, 0.0f);
        layer_mma(sm, j0, tw, kq,
                  g_h1[p], Wih0, 2048, 1024,
                  g_h0[p], Whh0, 1024, 0,
                  (t == 0) ? 8 : 0, acc, accc);    // t=0: feed is zero, skip
        #pragma unroll
        for (int e = 0; e < acc.num_elements; ++e) acc.x[e] += accc.x[e];
        wmma::store_matrix_sync(&sRed[kq][0][tw << 4], acc, 36, wmma::mem_row_major);
        __syncthreads();
        if (tid < 128) {
            int b = tid >> 3, u = tid & 7;
            const float* g0 = g_g0x + (((size_t)(t * TB + b)) << 12) + j0 + u;
            float gi = sRed[0][b][u]      + sRed[1][b][u]      + sRed[2][b][u]      + sRed[3][b][u]      + g0[0];
            float gf = sRed[0][b][8 + u]  + sRed[1][b][8 + u]  + sRed[2][b][8 + u]  + sRed[3][b][8 + u]  + g0[1024];
            float gg = sRed[0][b][16 + u] + sRed[1][b][16 + u] + sRed[2][b][16 + u] + sRed[3][b][16 + u] + g0[2048];
            float go = sRed[0][b][24 + u] + sRed[1][b][24 + u] + sRed[2][b][24 + u] + sRed[3][b][24 + u] + g0[3072];
            float cn = sigmoidf_(gf) * sC0[tid] + sigmoidf_(gi) * tanhf(gg);
            float hn = sigmoidf_(go) * tanhf(cn);
            sC0[tid] = cn;
            g_h0[p ^ 1][b * TH + j0 + u] = hn;
        }
        __syncthreads();
        tgt += GRID_R; grid_barrier(tgt);          // h0_new visible chip-wide

        // ------- layer 1: h0_new @ Wih1 + h1 @ Whh1 -------
        wmma::fill_fragment(acc, 0.0f);
        wmma::fill_fragment(accc, 0.0f);
        layer_mma(sm, j0, tw, kq,
                  g_h0[p ^ 1], Wih1, 1024, 0,
                  g_h1[p],     Whh1, 1024, 0,
                  0, acc, accc);
        #pragma unroll
        for (int e = 0; e < acc.num_elements; ++e) acc.x[e] += accc.x[e];
        wmma::store_matrix_sync(&sRed[kq][0][tw << 4], acc, 36, wmma::mem_row_major);
        __syncthreads();
        if (tid < 128) {
            int b = tid >> 3, u = tid & 7;
            float gi = sRed[0][b][u]      + sRed[1][b][u]      + sRed[2][b][u]      + sRed[3][b][u]      + sB1[u];
            float gf = sRed[0][b][8 + u]  + sRed[1][b][8 + u]  + sRed[2][b][8 + u]  + sRed[3][b][8 + u]  + sB1[8 + u];
            float gg = sRed[0][b][16 + u] + sRed[1][b][16 + u] + sRed[2][b][16 + u] + sRed[3][b][16 + u] + sB1[16 + u];
            float go = sRed[0][b][24 + u] + sRed[1][b][24 + u] + sRed[2][b][24 + u] + sRed[3][b][24 + u] + sB1[24 + u];
            float cn = sigmoidf_(gf) * sC1[tid] + sigmoidf_(gi) * tanhf(gg);
            float hn = sigmoidf_(go) * tanhf(cn);
            sC1[tid] = cn;
            g_h1[p ^ 1][b * TH + j0 + u] = hn;
            g_feats[((size_t)b * TT + t) * TH + j0 + u] = hn;
        }
        __syncthreads();
        tgt += GRID_R; grid_barrier(tgt);          // h1_new + feats visible
    }
}

// ---------------- generic tf32 WMMA GEMM: out = A @ W^T + b1 (+ b2) --------
// K fixed at 1024. CTA tile 64x64, 4 warps 2x2, warp 32x32 (2x2 m16n16k8).
// THREE=true enables 3xTF32 error compensation (for recurrence-feeding GEMMs).
template <bool THREE>
__global__ __launch_bounds__(128) void gemm_tf32_kernel(
    const float* __restrict__ A, int lda,
    const float* __restrict__ W, int ldw,
    const float* __restrict__ b1, const float* __restrict__ b2,
    float* __restrict__ out, size_t ldo)
{
    __shared__ float smem[2 * 64 * 40];
    float (*sA)[40] = (float(*)[40])smem;
    float (*sB)[40] = (float(*)[40])(smem + 64 * 40);

    int mblk = blockIdx.x << 6;
    int nblk = blockIdx.y << 6;
    int warp = threadIdx.x >> 5;
    int wm = (warp >> 1) * 32;
    int wn = (warp & 1) * 32;

    wmma::fragment<wmma::accumulator, 16, 16, 8, float> cf[2][2];
    #pragma unroll
    for (int mi = 0; mi < 2; ++mi)
        #pragma unroll
        for (int ni = 0; ni < 2; ++ni)
            wmma::fill_fragment(cf[mi][ni], 0.0f);

    for (int k0 = 0; k0 < 1024; k0 += 32) {
        #pragma unroll
        for (int i = 0; i < 4; ++i) {
            int slot = threadIdx.x + (i << 7);
            int row  = slot >> 3;
            int c4   = (slot & 7) << 2;
            *(float4*)&sA[row][c4] =
                *(const float4*)&A[(size_t)(mblk + row) * lda + k0 + c4];
            *(float4*)&sB[row][c4] =
                *(const float4*)&W[(size_t)(nblk + row) * ldw + k0 + c4];
        }
        __syncthreads();

        #pragma unroll
        for (int kk = 0; kk < 32; kk += 8) {
            wmma::fragment<wmma::matrix_a, 16, 16, 8,
                           wmma::precision::tf32, wmma::row_major> af[2], afl[2];
            wmma::fragment<wmma::matrix_b, 16, 16, 8,
                           wmma::precision::tf32, wmma::col_major> bf[2], bfl[2];
            #pragma unroll
            for (int i = 0; i < 2; ++i) {
                wmma::load_matrix_sync(af[i], &sA[wm + i * 16][kk], 40);
                wmma::load_matrix_sync(bf[i], &sB[wn + i * 16][kk], 40);
                #pragma unroll
                for (int e = 0; e < af[i].num_elements; ++e) {
                    float v  = af[i].x[e];
                    float hi = wmma::__float_to_tf32(v);
                    af[i].x[e] = hi;
                    if (THREE) afl[i].x[e] = wmma::__float_to_tf32(v - hi);
                }
                #pragma unroll
                for (int e = 0; e < bf[i].num_elements; ++e) {
                    float v  = bf[i].x[e];
                    float hi = wmma::__float_to_tf32(v);
                    bf[i].x[e] = hi;
                    if (THREE) bfl[i].x[e] = wmma::__float_to_tf32(v - hi);
                }
            }
            #pragma unroll
            for (int mi = 0; mi < 2; ++mi)
                #pragma unroll
                for (int ni = 0; ni < 2; ++ni) {
                    wmma::mma_sync(cf[mi][ni], af[mi], bf[ni], cf[mi][ni]);
                    if (THREE) {
                        wmma::mma_sync(cf[mi][ni], af[mi],  bfl[ni], cf[mi][ni]);
                        wmma::mma_sync(cf[mi][ni], afl[mi], bf[ni],  cf[mi][ni]);
                    }
                }
        }
        __syncthreads();
    }

    float (*sC)[68] = (float(*)[68])smem;
    #pragma unroll
    for (int mi = 0; mi < 2; ++mi)
        #pragma unroll
        for (int ni = 0; ni < 2; ++ni)
            wmma::store_matrix_sync(&sC[wm + mi * 16][wn + ni * 16],
                                    cf[mi][ni], 68, wmma::mem_row_major);
    __syncthreads();

    #pragma unroll
    for (int i = 0; i < 8; ++i) {
        int slot = threadIdx.x + (i << 7);
        int row  = slot >> 4;
        int c4   = (slot & 15) << 2;
        float4 v  = *(float4*)&sC[row][c4];
        float4 bv = *(const float4*)&b1[nblk + c4];
        v.x += bv.x; v.y += bv.y; v.z += bv.z; v.w += bv.w;
        if (b2) {
            float4 b2v = *(const float4*)&b2[nblk + c4];
            v.x += b2v.x; v.y += b2v.y; v.z += b2v.z; v.w += b2v.w;
        }
        *(float4*)&out[(size_t)(mblk + row) * ldo + nblk + c4] = v;
    }
}

// ---------------- launch ----------------------------------------------------
extern "C" void kernel_launch(void* const* d_in, const int* in_sizes, int n_in,
                              void* d_out, int out_size) {
    const int*   ids  = (const int*)d_in[0];
    const float* ench = (const float*)d_in[1];
    const float* encc = (const float*)d_in[2];
    const float* emb  = (const float*)d_in[3];
    const float* Wih0 = (const float*)d_in[4];
    const float* Whh0 = (const float*)d_in[5];
    const float* bih0 = (const float*)d_in[6];
    const float* bhh0 = (const float*)d_in[7];
    const float* Wih1 = (const float*)d_in[8];
    const float* Whh1 = (const float*)d_in[9];
    const float* bih1 = (const float*)d_in[10];
    const float* bhh1 = (const float*)d_in[11];
    const float* Wout = (const float*)d_in[12];
    const float* bout = (const float*)d_in[13];
    float* out = (float*)d_out;

    float *px = nullptr, *pg0x = nullptr, *pfeats = nullptr;
    cudaGetSymbolAddress((void**)&px,     g_x);
    cudaGetSymbolAddress((void**)&pg0x,   g_g0x);
    cudaGetSymbolAddress((void**)&pfeats, g_feats);
    cudaFuncSetAttribute(recur_kernel,
                         cudaFuncAttributeMaxDynamicSharedMemorySize,
                         SMEM_RECUR);

    // 1) gather embeddings
    embed_gather_kernel<<<TT * TB, 256>>>(ids, emb);

    // 2) hoisted input GEMM (3xTF32): g0x = x @ Wih0[:,:E]^T + bih0 + bhh0
    gemm_tf32_kernel<true><<<dim3(32, 64), 128>>>(px, TE, Wih0, TE + TH,
                                                  bih0, bhh0, pg0x,
                                                  (size_t)4 * TH);

    // 3) persistent recurrence over all 128 steps
    reset_kernel<<<1, 1>>>();
    recur_kernel<<<GRID_R, 256, SMEM_RECUR>>>(ench, encc, Wih0, Whh0,
                                              Wih1, Whh1, bih1, bhh1);

    // 4) output projection (1-pass tf32): logits = feats @ Wout^T + bout
    gemm_tf32_kernel<false><<<dim3(32, 500), 128>>>(pfeats, TH, Wout, TH,
                                                    bout, nullptr, out,
                                                    (size_t)TV);
}

// round 13
// speedup vs baseline: 1.4935x; 1.4490x over previous
#include <cuda_runtime.h>
#include <cuda_bf16.h>
#include <mma.h>

using namespace nvcuda;

#define TB 16      // batch
#define TT 128     // time steps
#define TE 1024    // embed dim
#define TH 1024    // hidden dim
#define TV 32000   // vocab
#define BH (TB*TH)

#define GRID_R 128   // persistent recurrence CTAs

// ---------------- scratch state (device globals: allocation-free) ----------
__device__ float g_x[(size_t)TT * TB * TE];        // [T][B][E] embeddings
__device__ float g_g0x[(size_t)TT * TB * 4 * TH];  // [T*B][4H] x-gates (+b0)
// weight planes, bf16 hi/lo, row-permuted: [mat][(j>>3)*32 + g*8 + (j&7)][1024]
// mat: 0=Wih0-feed-half  1=Whh0  2=Wih1  3=Whh1
__device__ __nv_bfloat16 g_Whi[4][(size_t)4096 * 1024];
__device__ __nv_bfloat16 g_Wlo[4][(size_t)4096 * 1024];
// activation planes (bf16 hi/lo), ping-pong
__device__ __nv_bfloat16 g_h0h[2][BH], g_h0l[2][BH];
__device__ __nv_bfloat16 g_h1h[2][BH], g_h1l[2][BH];
__device__ float g_feats[(size_t)TB * TT * TH];    // [B][T][H]
__device__ unsigned g_barctr;

// ---------------- embedding gather ----------------------------------------
__global__ void embed_gather_kernel(const int* __restrict__ ids,
                                    const float* __restrict__ embed) {
    int tb = blockIdx.x;            // t*TB + b
    int t  = tb >> 4;
    int b  = tb & 15;
    int id = ids[b * TT + t];
    const float4* src = (const float4*)(embed + (size_t)id * TE);
    float4*       dst = (float4*)(g_x + (size_t)tb * TE);
    dst[threadIdx.x] = src[threadIdx.x];   // 256 threads x float4 = 1024
}

__global__ void reset_kernel() { g_barctr = 0u; }

// ---------------- helpers ---------------------------------------------------
__device__ __forceinline__ unsigned ld_acq(const unsigned* p) {
    unsigned v;
    asm volatile("ld.acquire.gpu.u32 %0, [%1];" : "=r"(v) : "l"(p) : "memory");
    return v;
}
__device__ __forceinline__ void grid_barrier(unsigned tgt) {
    __syncthreads();
    if (threadIdx.x == 0) {
        __threadfence();
        atomicAdd(&g_barctr, 1u);
        while (ld_acq(&g_barctr) < tgt) {}
    }
    __syncthreads();
}
__device__ __forceinline__ void cp16(void* dst, const void* src) {
    unsigned d = (unsigned)__cvta_generic_to_shared(dst);
    asm volatile("cp.async.cg.shared.global [%0], [%1], 16;" :: "r"(d), "l"(src));
}
__device__ __forceinline__ float sigmoidf_(float x) {
    return 1.0f / (1.0f + __expf(-x));
}
__device__ __forceinline__ void bsplit(float v, __nv_bfloat16& hi,
                                       __nv_bfloat16& lo) {
    hi = __float2bfloat16(v);
    lo = __float2bfloat16(v - __bfloat162float(hi));
}

// ---------------- weight split: fp32 -> bf16 hi/lo planes ------------------
// grid (4096, 4), 256 threads; each thread handles 4 consecutive cols.
__global__ void wsplit_kernel(const float* __restrict__ Wih0,
                              const float* __restrict__ Whh0,
                              const float* __restrict__ Wih1,
                              const float* __restrict__ Whh1) {
    int R = blockIdx.x;                 // source row 0..4095 (= g*1024 + j)
    int m = blockIdx.y;                 // matrix id
    const float* src; int ld, co;
    if      (m == 0) { src = Wih0; ld = 2048; co = 1024; }
    else if (m == 1) { src = Whh0; ld = 1024; co = 0; }
    else if (m == 2) { src = Wih1; ld = 1024; co = 0; }
    else             { src = Whh1; ld = 1024; co = 0; }

    int g = R >> 10, j = R & 1023;
    size_t drow = ((size_t)(j >> 3) << 5) + (g << 3) + (j & 7);

    float4 v = *(const float4*)(src + (size_t)R * ld + co + (threadIdx.x << 2));
    union { __nv_bfloat16 b[4]; uint2 u; } ph, pl;
    bsplit(v.x, ph.b[0], pl.b[0]);
    bsplit(v.y, ph.b[1], pl.b[1]);
    bsplit(v.z, ph.b[2], pl.b[2]);
    bsplit(v.w, ph.b[3], pl.b[3]);
    size_t off = drow * 1024 + ((size_t)threadIdx.x << 2);
    *(uint2*)&g_Whi[m][off] = ph.u;
    *(uint2*)&g_Wlo[m][off] = pl.u;
}

// ---------------- smem layout (bytes) ---------------------------------------
#define OFF_WH  0                          // bf16 [2][32][136]
#define OFF_WL  (OFF_WH + 2*32*136*2)      // 17408
#define OFF_AH  (OFF_WL + 2*32*136*2)      // 34816: bf16 [2][16][136]
#define OFF_AL  (OFF_AH + 2*16*136*2)      // 43520
#define OFF_RED (OFF_AL + 2*16*136*2)      // 52224: float [4][16][36]
#define OFF_C0  (OFF_RED + 4*16*36*4)      // 61440: float[128]
#define OFF_C1  (OFF_C0 + 512)             // 61952
#define OFF_B1  (OFF_C1 + 512)             // 62464: float[32]
#define SMEM_RECUR (OFF_B1 + 128)          // 62592 B

// ---------------- fused two-phase mat-mul for one layer (bf16 hi/lo) -------
// CTA owns 32 gate rows (8 units x 4 gates), contiguous in the permuted planes.
// Warp w: tw=w&1 -> 16-row half; kq=w>>1 -> 32-col quarter of each 128 chunk.
// 16 chunks: phase0 (A0 @ W[m0]) then phase1 (A1 @ W[m1]).
__device__ __forceinline__ void layer_mma(
    char* smb, int cta, int tw, int kq,
    const __nv_bfloat16* A0h, const __nv_bfloat16* A0l, int m0,
    const __nv_bfloat16* A1h, const __nv_bfloat16* A1l, int m1,
    int i0,
    wmma::fragment<wmma::accumulator,16,16,16,float>& acc,
    wmma::fragment<wmma::accumulator,16,16,16,float>& accc)
{
    __nv_bfloat16 (*sWh)[32][136] = (__nv_bfloat16(*)[32][136])(smb + OFF_WH);
    __nv_bfloat16 (*sWl)[32][136] = (__nv_bfloat16(*)[32][136])(smb + OFF_WL);
    __nv_bfloat16 (*sAh)[16][136] = (__nv_bfloat16(*)[16][136])(smb + OFF_AH);
    __nv_bfloat16 (*sAl)[16][136] = (__nv_bfloat16(*)[16][136])(smb + OFF_AL);
    int tid = threadIdx.x;

    auto stage = [&](int i, int buf) {
        int ph = i >> 3;
        int k0 = (i & 7) << 7;
        const __nv_bfloat16* Ah = ph ? A1h : A0h;
        const __nv_bfloat16* Al = ph ? A1l : A0l;
        const __nv_bfloat16* Wh = g_Whi[ph ? m1 : m0] + ((size_t)cta << 15);
        const __nv_bfloat16* Wl = g_Wlo[ph ? m1 : m0] + ((size_t)cta << 15);
        #pragma unroll
        for (int l = 0; l < 2; ++l) {          // W: 32 rows x 16 float4 x2 planes
            int idx = tid + (l << 8);
            int rr = idx >> 4, f = idx & 15;
            size_t off = ((size_t)rr << 10) + k0 + (f << 3);
            cp16(&sWh[buf][rr][f << 3], Wh + off);
            cp16(&sWl[buf][rr][f << 3], Wl + off);
        }
        {                                       // A: 16 rows x 16 float4 x2 planes
            int b = tid >> 4, f = tid & 15;
            cp16(&sAh[buf][b][f << 3], Ah + b * TH + k0 + (f << 3));
            cp16(&sAl[buf][b][f << 3], Al + b * TH + k0 + (f << 3));
        }
        asm volatile("cp.async.commit_group;" ::: "memory");
    };

    stage(i0, 0);
    for (int i = i0; i < 16; ++i) {
        int buf = (i - i0) & 1;
        if (i + 1 < 16) {
            stage(i + 1, buf ^ 1);
            asm volatile("cp.async.wait_group 1;" ::: "memory");
        } else {
            asm volatile("cp.async.wait_group 0;" ::: "memory");
        }
        __syncthreads();
        #pragma unroll
        for (int ks = 0; ks < 2; ++ks) {
            int k = (kq << 5) + (ks << 4);
            wmma::fragment<wmma::matrix_a,16,16,16,__nv_bfloat16,wmma::row_major> ah, al;
            wmma::fragment<wmma::matrix_b,16,16,16,__nv_bfloat16,wmma::col_major> bh, bl;
            wmma::load_matrix_sync(ah, &sAh[buf][0][k], 136);
            wmma::load_matrix_sync(al, &sAl[buf][0][k], 136);
            wmma::load_matrix_sync(bh, &sWh[buf][tw << 4][k], 136);
            wmma::load_matrix_sync(bl, &sWl[buf][tw << 4][k], 136);
            wmma::mma_sync(acc,  ah, bh, acc);
            wmma::mma_sync(accc, ah, bl, accc);
            wmma::mma_sync(accc, al, bh, accc);
        }
        __syncthreads();
    }
}

// ---------------- persistent recurrence kernel ------------------------------
__global__ void __launch_bounds__(256, 1) recur_kernel(
    const float* __restrict__ eh, const float* __restrict__ ec,
    const float* __restrict__ bih1, const float* __restrict__ bhh1)
{
    extern __shared__ char smb[];
    float (*sRed)[16][36] = (float(*)[16][36])(smb + OFF_RED);
    float* sC0 = (float*)(smb + OFF_C0);
    float* sC1 = (float*)(smb + OFF_C1);
    float* sB1 = (float*)(smb + OFF_B1);

    int cta = blockIdx.x;
    int j0  = cta << 3;               // 8 hidden units per CTA
    int tid = threadIdx.x;
    int w   = tid >> 5;
    int tw  = w & 1;
    int kq  = w >> 1;

    // init: c-state into smem (lives there all 128 steps), h planes into gmem
    if (tid < 128) {
        int b = tid >> 3, u = tid & 7;
        int gidx = b * TH + j0 + u;
        sC0[tid] = ec[gidx];
        sC1[tid] = ec[BH + gidx];
        __nv_bfloat16 hh, hl;
        bsplit(eh[gidx], hh, hl);
        g_h0h[0][gidx] = hh; g_h0l[0][gidx] = hl;
        bsplit(eh[BH + gidx], hh, hl);
        g_h1h[0][gidx] = hh; g_h1l[0][gidx] = hl;
    } else if (tid < 160) {
        int r = tid - 128;
        int g = r >> 3, u = r & 7;
        sB1[r] = bih1[g * TH + j0 + u] + bhh1[g * TH + j0 + u];
    }
    unsigned tgt = GRID_R;
    grid_barrier(tgt);

    for (int t = 0; t < TT; ++t) {
        int p = t & 1;
        wmma::fragment<wmma::accumulator,16,16,16,float> acc, accc;

        // ------- layer 0: feed @ Wih0[:,1024:] + h0 @ Whh0 (+ g0x) -------
        wmma::fill_fragment(acc, 0.0f);
        wmma::fill_fragment(accc, 0.0f);
        layer_mma(smb, cta, tw, kq,
                  g_h1h[p], g_h1l[p], 0,
                  g_h0h[p], g_h0l[p], 1,
                  (t == 0) ? 8 : 0, acc, accc);  // t=0: feed is zero, skip
        #pragma unroll
        for (int e = 0; e < acc.num_elements; ++e) acc.x[e] += accc.x[e];
        wmma::store_matrix_sync(&sRed[kq][0][tw << 4], acc, 36, wmma::mem_row_major);
        __syncthreads();
        if (tid < 128) {
            int b = tid >> 3, u = tid & 7;
            const float* g0 = g_g0x + (((size_t)(t * TB + b)) << 12) + j0 + u;
            float gi = sRed[0][b][u]      + sRed[1][b][u]      + sRed[2][b][u]      + sRed[3][b][u]      + g0[0];
            float gf = sRed[0][b][8 + u]  + sRed[1][b][8 + u]  + sRed[2][b][8 + u]  + sRed[3][b][8 + u]  + g0[1024];
            float gg = sRed[0][b][16 + u] + sRed[1][b][16 + u] + sRed[2][b][16 + u] + sRed[3][b][16 + u] + g0[2048];
            float go = sRed[0][b][24 + u] + sRed[1][b][24 + u] + sRed[2][b][24 + u] + sRed[3][b][24 + u] + g0[3072];
            float cn = sigmoidf_(gf) * sC0[tid] + sigmoidf_(gi) * tanhf(gg);
            float hn = sigmoidf_(go) * tanhf(cn);
            sC0[tid] = cn;
            int gidx = b * TH + j0 + u;
            __nv_bfloat16 hh, hl; bsplit(hn, hh, hl);
            g_h0h[p ^ 1][gidx] = hh; g_h0l[p ^ 1][gidx] = hl;
        }
        __syncthreads();
        tgt += GRID_R; grid_barrier(tgt);          // h0_new visible chip-wide

        // ------- layer 1: h0_new @ Wih1 + h1 @ Whh1 -------
        wmma::fill_fragment(acc, 0.0f);
        wmma::fill_fragment(accc, 0.0f);
        layer_mma(smb, cta, tw, kq,
                  g_h0h[p ^ 1], g_h0l[p ^ 1], 2,
                  g_h1h[p],     g_h1l[p],     3,
                  0, acc, accc);
        #pragma unroll
        for (int e = 0; e < acc.num_elements; ++e) acc.x[e] += accc.x[e];
        wmma::store_matrix_sync(&sRed[kq][0][tw << 4], acc, 36, wmma::mem_row_major);
        __syncthreads();
        if (tid < 128) {
            int b = tid >> 3, u = tid & 7;
            float gi = sRed[0][b][u]      + sRed[1][b][u]      + sRed[2][b][u]      + sRed[3][b][u]      + sB1[u];
            float gf = sRed[0][b][8 + u]  + sRed[1][b][8 + u]  + sRed[2][b][8 + u]  + sRed[3][b][8 + u]  + sB1[8 + u];
            float gg = sRed[0][b][16 + u] + sRed[1][b][16 + u] + sRed[2][b][16 + u] + sRed[3][b][16 + u] + sB1[16 + u];
            float go = sRed[0][b][24 + u] + sRed[1][b][24 + u] + sRed[2][b][24 + u] + sRed[3][b][24 + u] + sB1[24 + u];
            float cn = sigmoidf_(gf) * sC1[tid] + sigmoidf_(gi) * tanhf(gg);
            float hn = sigmoidf_(go) * tanhf(cn);
            sC1[tid] = cn;
            int gidx = b * TH + j0 + u;
            __nv_bfloat16 hh, hl; bsplit(hn, hh, hl);
            g_h1h[p ^ 1][gidx] = hh; g_h1l[p ^ 1][gidx] = hl;
            g_feats[((size_t)b * TT + t) * TH + j0 + u] = hn;
        }
        __syncthreads();
        tgt += GRID_R; grid_barrier(tgt);          // h1_new + feats visible
    }
}

// ---------------- generic tf32 WMMA GEMM: out = A @ W^T + b1 (+ b2) --------
// K fixed at 1024. CTA tile 64x64, 4 warps 2x2, warp 32x32 (2x2 m16n16k8).
// THREE=true enables 3xTF32 error compensation.
template <bool THREE>
__global__ __launch_bounds__(128) void gemm_tf32_kernel(
    const float* __restrict__ A, int lda,
    const float* __restrict__ W, int ldw,
    const float* __restrict__ b1, const float* __restrict__ b2,
    float* __restrict__ out, size_t ldo)
{
    __shared__ float smem[2 * 64 * 40];
    float (*sA)[40] = (float(*)[40])smem;
    float (*sB)[40] = (float(*)[40])(smem + 64 * 40);

    int mblk = blockIdx.x << 6;
    int nblk = blockIdx.y << 6;
    int warp = threadIdx.x >> 5;
    int wm = (warp >> 1) * 32;
    int wn = (warp & 1) * 32;

    wmma::fragment<wmma::accumulator, 16, 16, 8, float> cf[2][2];
    #pragma unroll
    for (int mi = 0; mi < 2; ++mi)
        #pragma unroll
        for (int ni = 0; ni < 2; ++ni)
            wmma::fill_fragment(cf[mi][ni], 0.0f);

    for (int k0 = 0; k0 < 1024; k0 += 32) {
        #pragma unroll
        for (int i = 0; i < 4; ++i) {
            int slot = threadIdx.x + (i << 7);
            int row  = slot >> 3;
            int c4   = (slot & 7) << 2;
            *(float4*)&sA[row][c4] =
                *(const float4*)&A[(size_t)(mblk + row) * lda + k0 + c4];
            *(float4*)&sB[row][c4] =
                *(const float4*)&W[(size_t)(nblk + row) * ldw + k0 + c4];
        }
        __syncthreads();

        #pragma unroll
        for (int kk = 0; kk < 32; kk += 8) {
            wmma::fragment<wmma::matrix_a, 16, 16, 8,
                           wmma::precision::tf32, wmma::row_major> af[2], afl[2];
            wmma::fragment<wmma::matrix_b, 16, 16, 8,
                           wmma::precision::tf32, wmma::col_major> bf[2], bfl[2];
            #pragma unroll
            for (int i = 0; i < 2; ++i) {
                wmma::load_matrix_sync(af[i], &sA[wm + i * 16][kk], 40);
                wmma::load_matrix_sync(bf[i], &sB[wn + i * 16][kk], 40);
                #pragma unroll
                for (int e = 0; e < af[i].num_elements; ++e) {
                    float v  = af[i].x[e];
                    float hi = wmma::__float_to_tf32(v);
                    af[i].x[e] = hi;
                    if (THREE) afl[i].x[e] = wmma::__float_to_tf32(v - hi);
                }
                #pragma unroll
                for (int e = 0; e < bf[i].num_elements; ++e) {
                    float v  = bf[i].x[e];
                    float hi = wmma::__float_to_tf32(v);
                    bf[i].x[e] = hi;
                    if (THREE) bfl[i].x[e] = wmma::__float_to_tf32(v - hi);
                }
            }
            #pragma unroll
            for (int mi = 0; mi < 2; ++mi)
                #pragma unroll
                for (int ni = 0; ni < 2; ++ni) {
                    wmma::mma_sync(cf[mi][ni], af[mi], bf[ni], cf[mi][ni]);
                    if (THREE) {
                        wmma::mma_sync(cf[mi][ni], af[mi],  bfl[ni], cf[mi][ni]);
                        wmma::mma_sync(cf[mi][ni], afl[mi], bf[ni],  cf[mi][ni]);
                    }
                }
        }
        __syncthreads();
    }

    float (*sC)[68] = (float(*)[68])smem;
    #pragma unroll
    for (int mi = 0; mi < 2; ++mi)
        #pragma unroll
        for (int ni = 0; ni < 2; ++ni)
            wmma::store_matrix_sync(&sC[wm + mi * 16][wn + ni * 16],
                                    cf[mi][ni], 68, wmma::mem_row_major);
    __syncthreads();

    #pragma unroll
    for (int i = 0; i < 8; ++i) {
        int slot = threadIdx.x + (i << 7);
        int row  = slot >> 4;
        int c4   = (slot & 15) << 2;
        float4 v  = *(float4*)&sC[row][c4];
        float4 bv = *(const float4*)&b1[nblk + c4];
        v.x += bv.x; v.y += bv.y; v.z += bv.z; v.w += bv.w;
        if (b2) {
            float4 b2v = *(const float4*)&b2[nblk + c4];
            v.x += b2v.x; v.y += b2v.y; v.z += b2v.z; v.w += b2v.w;
        }
        *(float4*)&out[(size_t)(mblk + row) * ldo + nblk + c4] = v;
    }
}

// ---------------- launch ----------------------------------------------------
extern "C" void kernel_launch(void* const* d_in, const int* in_sizes, int n_in,
                              void* d_out, int out_size) {
    const int*   ids  = (const int*)d_in[0];
    const float* ench = (const float*)d_in[1];
    const float* encc = (const float*)d_in[2];
    const float* emb  = (const float*)d_in[3];
    const float* Wih0 = (const float*)d_in[4];
    const float* Whh0 = (const float*)d_in[5];
    const float* bih0 = (const float*)d_in[6];
    const float* bhh0 = (const float*)d_in[7];
    const float* Wih1 = (const float*)d_in[8];
    const float* Whh1 = (const float*)d_in[9];
    const float* bih1 = (const float*)d_in[10];
    const float* bhh1 = (const float*)d_in[11];
    const float* Wout = (const float*)d_in[12];
    const float* bout = (const float*)d_in[13];
    float* out = (float*)d_out;

    float *px = nullptr, *pg0x = nullptr, *pfeats = nullptr;
    cudaGetSymbolAddress((void**)&px,     g_x);
    cudaGetSymbolAddress((void**)&pg0x,   g_g0x);
    cudaGetSymbolAddress((void**)&pfeats, g_feats);
    cudaFuncSetAttribute(recur_kernel,
                         cudaFuncAttributeMaxDynamicSharedMemorySize,
                         SMEM_RECUR);

    // 1) gather embeddings + split recurrence weights into bf16 hi/lo planes
    embed_gather_kernel<<<TT * TB, 256>>>(ids, emb);
    wsplit_kernel<<<dim3(4096, 4), 256>>>(Wih0, Whh0, Wih1, Whh1);

    // 2) hoisted input GEMM (3xTF32): g0x = x @ Wih0[:,:E]^T + bih0 + bhh0
    gemm_tf32_kernel<true><<<dim3(32, 64), 128>>>(px, TE, Wih0, TE + TH,
                                                  bih0, bhh0, pg0x,
                                                  (size_t)4 * TH);

    // 3) persistent recurrence over all 128 steps (bf16 hi/lo tensor cores)
    reset_kernel<<<1, 1>>>();
    recur_kernel<<<GRID_R, 256, SMEM_RECUR>>>(ench, encc, bih1, bhh1);

    // 4) output projection (1-pass tf32): logits = feats @ Wout^T + bout
    gemm_tf32_kernel<false><<<dim3(32, 500), 128>>>(pfeats, TH, Wout, TH,
                                                    bout, nullptr, out,
                                                    (size_t)TV);
}